// round 2
// baseline (speedup 1.0000x reference)
#include <cuda_runtime.h>
#include <cuda_bf16.h>
#include <math.h>

// ---------------- problem constants ----------------
#define NNODES 40960
#define NEDGES 163840
#define NGRAPH 1024
#define F0 78
#define F1D 78
#define F2D 156
#define F3D 312

// ---------------- scratch (static device memory; no allocations) ----------
__device__ float g_B1[NNODES * F3D];
__device__ float g_B2[NNODES * F3D];
__device__ float g_dinv[NNODES];
__device__ int   g_cnt[NNODES];
__device__ int   g_rowptr[NNODES + 1];
__device__ int   g_cur[NNODES];
__device__ int   g_col[NEDGES];
__device__ float g_G[NGRAPH * F3D];
__device__ float g_G1[NGRAPH * 1024];
__device__ float g_XC[NGRAPH * 384];
__device__ float g_Y2[NGRAPH * 3872];
__device__ float g_Y1[NGRAPH * 416];
__device__ float g_F1[NGRAPH * 1024];
__device__ float g_F2[NGRAPH * 512];
__device__ float g_Wc2t[750 * 256];
__device__ float g_Wc1t[750 * 256];

// ---------------- CSR build ----------------
__global__ void k_hist(const int* __restrict__ ei, int* __restrict__ cnt, int e) {
    int i = blockIdx.x * blockDim.x + threadIdx.x;
    if (i < e) atomicAdd(&cnt[ei[e + i]], 1);
}

// one block, 1024 threads: exclusive scan of cnt -> rowptr/cur, dinv from deg+1
__global__ void k_scan(const int* __restrict__ cnt, int* __restrict__ rowptr,
                       int* __restrict__ cur, float* __restrict__ dinv) {
    __shared__ int ssum[1024];
    int t = threadIdx.x;
    const int CH = NNODES / 1024;     // 40
    int base = t * CH;
    int s = 0;
    for (int i = 0; i < CH; i++) s += cnt[base + i];
    ssum[t] = s;
    __syncthreads();
    for (int off = 1; off < 1024; off <<= 1) {
        int v = (t >= off) ? ssum[t - off] : 0;
        __syncthreads();
        ssum[t] += v;
        __syncthreads();
    }
    int run = ssum[t] - s;            // exclusive
    for (int i = 0; i < CH; i++) {
        int c = cnt[base + i];
        rowptr[base + i] = run;
        cur[base + i]    = run;
        dinv[base + i]   = rsqrtf((float)c + 1.0f);
        run += c;
    }
    if (t == 1023) rowptr[NNODES] = run;
}

__global__ void k_scatter(const int* __restrict__ ei, int* __restrict__ cur,
                          int* __restrict__ col, int e) {
    int i = blockIdx.x * blockDim.x + threadIdx.x;
    if (i >= e) return;
    int s = ei[i], d = ei[e + i];
    int pos = atomicAdd(&cur[d], 1);
    col[pos] = s;
}

// ---------------- CSR gather aggregation --------------------------------
// hws rows are already scaled by dinv[src] (done in GEMM epilogue).
// out[d,f] = dinv[d] * (hws[d,f] + sum_{s in nbr(d)} hws[s,f]) + bias[f]
// doPool: relu then per-graph atomicMax into pool (out not written).
__global__ void k_aggr(const float* __restrict__ hws, const int* __restrict__ rowptr,
                       const int* __restrict__ col, const float* __restrict__ dinv,
                       const float* __restrict__ bias, float* __restrict__ out,
                       const int* __restrict__ batch, float* __restrict__ pool,
                       int F, int doPool) {
    int node = blockIdx.x * (blockDim.x >> 5) + (threadIdx.x >> 5);
    if (node >= NNODES) return;
    int lane = threadIdx.x & 31;
    int rs = rowptr[node], re = rowptr[node + 1];
    float di = dinv[node];
    float acc[10];
    const float* selfp = hws + (size_t)node * F;
#pragma unroll 10
    for (int c = 0; c < 10; c++) {
        int f = lane + c * 32;
        acc[c] = (f < F) ? selfp[f] : 0.f;
    }
    for (int e = rs; e < re; e++) {
        int s = col[e];
        const float* p = hws + (size_t)s * F;
#pragma unroll 10
        for (int c = 0; c < 10; c++) {
            int f = lane + c * 32;
            if (f < F) acc[c] += p[f];
        }
    }
    if (doPool) {
        int gslot = batch[node];
        float* pp = pool + (size_t)gslot * F;
#pragma unroll 10
        for (int c = 0; c < 10; c++) {
            int f = lane + c * 32;
            if (f < F) {
                float v = fmaxf(acc[c] * di + bias[f], 0.f);
                atomicMax((int*)&pp[f], __float_as_int(v));
            }
        }
    } else {
        float* op = out + (size_t)node * F;
#pragma unroll 10
        for (int c = 0; c < 10; c++) {
            int f = lane + c * 32;
            if (f < F) op[f] = acc[c] * di + bias[f];
        }
    }
}

// ---------------- tiled SGEMM: 128x64 tile, 8x4 microtile --------------------
// C[m*ldc+coff+n] = act( (reluA? relu(A):A) @ B  * (rs? rs[m]:1) + bias )
__global__ void k_sgemm(const float* __restrict__ A, const float* __restrict__ B,
                        float* __restrict__ C, int M, int N, int K,
                        const float* __restrict__ bias, int doRelu, int reluA,
                        int ldc, int coff, const float* __restrict__ rs) {
    __shared__ float As[8][128];
    __shared__ float Bs[8][64];
    int tid = threadIdx.x;
    int tx = tid & 15;            // N dir: 16*4 = 64
    int ty = tid >> 4;            // M dir: 16*8 = 128
    int bm = blockIdx.y * 128, bn = blockIdx.x * 64;
    float acc[8][4] = {};
    for (int k0 = 0; k0 < K; k0 += 8) {
        for (int i = tid; i < 128 * 8; i += 256) {
            int r = i >> 3, c = i & 7;
            int m = bm + r, k = k0 + c;
            float v = (m < M && k < K) ? A[(size_t)m * K + k] : 0.f;
            if (reluA) v = fmaxf(v, 0.f);
            As[c][r] = v;
        }
        for (int i = tid; i < 8 * 64; i += 256) {
            int r = i >> 6, c = i & 63;
            int k = k0 + r, n = bn + c;
            Bs[r][c] = (k < K && n < N) ? B[(size_t)k * N + n] : 0.f;
        }
        __syncthreads();
#pragma unroll
        for (int kk = 0; kk < 8; kk++) {
            float a[8], b[4];
#pragma unroll
            for (int i = 0; i < 8; i++) a[i] = As[kk][ty * 8 + i];
#pragma unroll
            for (int j = 0; j < 4; j++) b[j] = Bs[kk][tx * 4 + j];
#pragma unroll
            for (int i = 0; i < 8; i++)
#pragma unroll
                for (int j = 0; j < 4; j++) acc[i][j] += a[i] * b[j];
        }
        __syncthreads();
    }
#pragma unroll
    for (int i = 0; i < 8; i++) {
        int m = bm + ty * 8 + i;
        if (m >= M) continue;
        float scale = rs ? rs[m] : 1.f;
#pragma unroll
        for (int j = 0; j < 4; j++) {
            int n = bn + tx * 4 + j;
            if (n >= N) continue;
            float v = acc[i][j] * scale + (bias ? bias[n] : 0.f);
            if (doRelu) v = fmaxf(v, 0.f);
            C[(size_t)m * ldc + coff + n] = v;
        }
    }
}

// ---------------- transpose Wc[32][750][8] -> Wt[750][256] -------------------
__global__ void k_transw(const float* __restrict__ W, float* __restrict__ Wt) {
    int i = blockIdx.x * blockDim.x + threadIdx.x;
    if (i >= 750 * 256) return;
    int c = i >> 8, ok = i & 255;
    int o = ok >> 3, k = ok & 7;
    Wt[i] = W[((size_t)o * 750 + c) * 8 + k];
}

// ---------------- protein branch 2: factored conv via class-histogram T ------
__global__ void k_branch2(const int* __restrict__ t2, const float* __restrict__ Wc2t,
                          const float* __restrict__ embw, const float* __restrict__ bc2,
                          float* __restrict__ Y2) {
    __shared__ float Tl[26 * 256];
    __shared__ float embs[26 * 128];
    __shared__ int   t2s[750];
    int b = blockIdx.x, tid = threadIdx.x;
    for (int i = tid; i < 26 * 256; i += 256) Tl[i] = 0.f;
    for (int i = tid; i < 26 * 128; i += 256) embs[i] = embw[i];
    for (int i = tid; i < 750; i += 256) t2s[i] = t2[(size_t)b * 750 + i];
    __syncthreads();
    for (int c = 0; c < 750; c++)
        Tl[t2s[c] * 256 + tid] += Wc2t[(size_t)c * 256 + tid];
    __syncthreads();
    for (int idx = tid; idx < 32 * 121; idx += 256) {
        int o = idx / 121, l = idx - o * 121;
        float acc = bc2[o];
        for (int v = 0; v < 26; v++) {
#pragma unroll
            for (int k = 0; k < 8; k++)
                acc += Tl[v * 256 + o * 8 + k] * embs[v * 128 + l + k];
        }
        Y2[(size_t)b * 3872 + idx] = acc;
    }
}

// ---------------- protein branch 1: direct conv --------------------------
__global__ void k_conv1(const float* __restrict__ t1, const float* __restrict__ Wc1t,
                        const float* __restrict__ bc1, float* __restrict__ Y1) {
    __shared__ float sin_[50 * 20];
    int b = blockIdx.x, tid = threadIdx.x;
    int o = tid >> 3, k = tid & 7;
    float acc[13] = {};
    for (int c0 = 0; c0 < 750; c0 += 50) {
        for (int i = tid; i < 1000; i += 256)
            sin_[i] = t1[(size_t)b * 15000 + c0 * 20 + i];
        __syncthreads();
        for (int cc = 0; cc < 50; cc++) {
            float w = Wc1t[(size_t)(c0 + cc) * 256 + tid];
#pragma unroll
            for (int l = 0; l < 13; l++)
                acc[l] += w * sin_[cc * 20 + k + l];
        }
        __syncthreads();
    }
#pragma unroll
    for (int l = 0; l < 13; l++) {
        float v = acc[l];
        v += __shfl_down_sync(0xffffffffu, v, 4, 8);
        v += __shfl_down_sync(0xffffffffu, v, 2, 8);
        v += __shfl_down_sync(0xffffffffu, v, 1, 8);
        if (k == 0) Y1[(size_t)b * 416 + o * 13 + l] = v + bc1[o];
    }
}

// ---------------- final projection -------------------------------------------
__global__ void k_out(const float* __restrict__ F2w, const float* __restrict__ Wo,
                      const float* __restrict__ bo, float* __restrict__ out) {
    int warp = (blockIdx.x * blockDim.x + threadIdx.x) >> 5;
    int lane = threadIdx.x & 31;
    if (warp >= NGRAPH) return;
    float s = 0.f;
    for (int i = lane; i < 512; i += 32) s += F2w[(size_t)warp * 512 + i] * Wo[i];
#pragma unroll
    for (int off = 16; off; off >>= 1) s += __shfl_down_sync(0xffffffffu, s, off);
    if (lane == 0) out[warp] = s + bo[0];
}

// ---------------- host orchestration ----------------
static inline dim3 gemm_grid(int M, int N) { return dim3((N + 63) / 64, (M + 127) / 128); }

extern "C" void kernel_launch(void* const* d_in, const int* in_sizes, int n_in,
                              void* d_out, int out_size) {
    const float* x   = (const float*)d_in[0];
    const int*   ei  = (const int*)  d_in[1];
    const int*   bat = (const int*)  d_in[2];
    const float* t1  = (const float*)d_in[3];
    const int*   t2  = (const int*)  d_in[4];
    const float *W1 = (const float*)d_in[5],  *b1 = (const float*)d_in[6];
    const float *W2 = (const float*)d_in[7],  *b2 = (const float*)d_in[8];
    const float *W3 = (const float*)d_in[9],  *b3 = (const float*)d_in[10];
    const float *Wg1= (const float*)d_in[11], *bg1= (const float*)d_in[12];
    const float *Wg2= (const float*)d_in[13], *bg2= (const float*)d_in[14];
    const float *emb= (const float*)d_in[15];
    const float *Wc2= (const float*)d_in[16], *bc2= (const float*)d_in[17];
    const float *Wxt2=(const float*)d_in[18], *bxt2=(const float*)d_in[19];
    const float *Wc1= (const float*)d_in[20], *bc1= (const float*)d_in[21];
    const float *Wxt1=(const float*)d_in[22], *bxt1=(const float*)d_in[23];
    const float *Wf1= (const float*)d_in[24], *bf1= (const float*)d_in[25];
    const float *Wf2= (const float*)d_in[26], *bf2= (const float*)d_in[27];
    const float *Wo = (const float*)d_in[28], *bo = (const float*)d_in[29];
    float* out = (float*)d_out;

    float *B1, *B2, *dinv, *G, *G1, *XC, *Y2, *Y1, *Fb1, *Fb2, *Wc2t, *Wc1t;
    int *cnt, *rowptr, *cur, *col;
    cudaGetSymbolAddress((void**)&B1, g_B1);
    cudaGetSymbolAddress((void**)&B2, g_B2);
    cudaGetSymbolAddress((void**)&dinv, g_dinv);
    cudaGetSymbolAddress((void**)&cnt, g_cnt);
    cudaGetSymbolAddress((void**)&rowptr, g_rowptr);
    cudaGetSymbolAddress((void**)&cur, g_cur);
    cudaGetSymbolAddress((void**)&col, g_col);
    cudaGetSymbolAddress((void**)&G, g_G);
    cudaGetSymbolAddress((void**)&G1, g_G1);
    cudaGetSymbolAddress((void**)&XC, g_XC);
    cudaGetSymbolAddress((void**)&Y2, g_Y2);
    cudaGetSymbolAddress((void**)&Y1, g_Y1);
    cudaGetSymbolAddress((void**)&Fb1, g_F1);
    cudaGetSymbolAddress((void**)&Fb2, g_F2);
    cudaGetSymbolAddress((void**)&Wc2t, g_Wc2t);
    cudaGetSymbolAddress((void**)&Wc1t, g_Wc1t);

    const int N = NNODES, E = NEDGES;
    const int aggBlocks = (N + 7) / 8;     // 8 warps/block, warp per node

    // ---- CSR build + normalization ----
    cudaMemsetAsync(cnt, 0, N * sizeof(int));
    cudaMemsetAsync(G, 0, (size_t)NGRAPH * F3D * sizeof(float));
    k_hist   <<<(E + 255) / 256, 256>>>(ei, cnt, E);
    k_scan   <<<1, 1024>>>(cnt, rowptr, cur, dinv);
    k_scatter<<<(E + 255) / 256, 256>>>(ei, cur, col, E);

    // ---- GCN layer 1 ----
    k_sgemm<<<gemm_grid(N, F1D), 256>>>(x, W1, B2, N, F1D, F0, nullptr, 0, 0, F1D, 0, dinv);
    k_aggr <<<aggBlocks, 256>>>(B2, rowptr, col, dinv, b1, B1, nullptr, nullptr, F1D, 0);
    // ---- layer 2 ----
    k_sgemm<<<gemm_grid(N, F2D), 256>>>(B1, W2, B2, N, F2D, F1D, nullptr, 0, 1, F2D, 0, dinv);
    k_aggr <<<aggBlocks, 256>>>(B2, rowptr, col, dinv, b2, B1, nullptr, nullptr, F2D, 0);
    // ---- layer 3 (fused relu + per-graph max pool) ----
    k_sgemm<<<gemm_grid(N, F3D), 256>>>(B1, W3, B2, N, F3D, F2D, nullptr, 0, 1, F3D, 0, dinv);
    k_aggr <<<aggBlocks, 256>>>(B2, rowptr, col, dinv, b3, nullptr, bat, G, F3D, 1);

    // ---- graph head ----
    k_sgemm<<<gemm_grid(NGRAPH, 1024), 256>>>(G, Wg1, G1, NGRAPH, 1024, F3D, bg1, 1, 0, 1024, 0, nullptr);
    k_sgemm<<<gemm_grid(NGRAPH, 128), 256>>>(G1, Wg2, XC, NGRAPH, 128, 1024, bg2, 0, 0, 384, 0, nullptr);

    // ---- protein branch 2 -> XC[:,256:384] ----
    k_transw<<<750, 256>>>(Wc2, Wc2t);
    k_branch2<<<NGRAPH, 256>>>(t2, Wc2t, emb, bc2, Y2);
    k_sgemm<<<gemm_grid(NGRAPH, 128), 256>>>(Y2, Wxt2, XC, NGRAPH, 128, 3872, bxt2, 0, 0, 384, 256, nullptr);

    // ---- protein branch 1 -> XC[:,128:256] ----
    k_transw<<<750, 256>>>(Wc1, Wc1t);
    k_conv1<<<NGRAPH, 256>>>(t1, Wc1t, bc1, Y1);
    k_sgemm<<<gemm_grid(NGRAPH, 128), 256>>>(Y1, Wxt1, XC, NGRAPH, 128, 416, bxt1, 0, 0, 384, 128, nullptr);

    // ---- fusion head ----
    k_sgemm<<<gemm_grid(NGRAPH, 1024), 256>>>(XC, Wf1, Fb1, NGRAPH, 1024, 384, bf1, 1, 0, 1024, 0, nullptr);
    k_sgemm<<<gemm_grid(NGRAPH, 512), 256>>>(Fb1, Wf2, Fb2, NGRAPH, 512, 1024, bf2, 1, 0, 512, 0, nullptr);
    k_out<<<(NGRAPH * 32 + 255) / 256, 256>>>(Fb2, Wo, bo, out);
}

// round 3
// speedup vs baseline: 2.2978x; 2.2978x over previous
#include <cuda_runtime.h>
#include <cuda_bf16.h>
#include <math.h>

#define NNODES 40960
#define NEDGES 163840
#define NGRAPH 1024
typedef unsigned long long ULL;

// padded feature dims (multiples of 16)
#define P1 80
#define P2 160
#define P3 320

// ---------------- static scratch ----------------
__device__ __align__(16) float g_X80[NNODES * P1];
__device__ __align__(16) float g_B1[NNODES * P3];
__device__ __align__(16) float g_B2[NNODES * P3];
__device__ float g_dinv[NNODES];
__device__ int   g_cnt[NNODES];
__device__ int   g_rowptr[NNODES + 1];
__device__ int   g_cur[NNODES];
__device__ int   g_col[NEDGES];
__device__ __align__(16) float g_G[NGRAPH * P3];
__device__ __align__(16) float g_G1[NGRAPH * 1024];
__device__ __align__(16) float g_XC[NGRAPH * 384];
__device__ __align__(16) float g_Y2[NGRAPH * 3872];
__device__ __align__(16) float g_Y1[NGRAPH * 416];
__device__ __align__(16) float g_F1[NGRAPH * 1024];
__device__ __align__(16) float g_F2[NGRAPH * 512];
__device__ __align__(16) float g_Wc2t[750 * 256];
__device__ __align__(16) float g_Wc1t[750 * 256];
__device__ __align__(16) float g_W1p[P1 * P1];
__device__ __align__(16) float g_W2p[P1 * P2];
__device__ __align__(16) float g_W3p[P2 * P3];
__device__ __align__(16) float g_Wg1p[P3 * 1024];

// ---------------- CSR build ----------------
__global__ void k_hist(const int* __restrict__ ei, int* __restrict__ cnt, int e) {
    int i = blockIdx.x * blockDim.x + threadIdx.x;
    if (i < e) atomicAdd(&cnt[ei[e + i]], 1);
}
__global__ void k_scan(const int* __restrict__ cnt, int* __restrict__ rowptr,
                       int* __restrict__ cur, float* __restrict__ dinv) {
    __shared__ int ssum[1024];
    int t = threadIdx.x;
    const int CH = NNODES / 1024;
    int base = t * CH;
    int s = 0;
    for (int i = 0; i < CH; i++) s += cnt[base + i];
    ssum[t] = s;
    __syncthreads();
    for (int off = 1; off < 1024; off <<= 1) {
        int v = (t >= off) ? ssum[t - off] : 0;
        __syncthreads();
        ssum[t] += v;
        __syncthreads();
    }
    int run = ssum[t] - s;
    for (int i = 0; i < CH; i++) {
        int c = cnt[base + i];
        rowptr[base + i] = run;
        cur[base + i]    = run;
        dinv[base + i]   = rsqrtf((float)c + 1.0f);
        run += c;
    }
    if (t == 1023) rowptr[NNODES] = run;
}
__global__ void k_scatter(const int* __restrict__ ei, int* __restrict__ cur,
                          int* __restrict__ col, int e) {
    int i = blockIdx.x * blockDim.x + threadIdx.x;
    if (i >= e) return;
    int s = ei[i], d = ei[e + i];
    int pos = atomicAdd(&cur[d], 1);
    col[pos] = s;
}

// ---------------- padding kernels ----------------
__global__ void k_padx(const float* __restrict__ x, float4* __restrict__ xp) {
    int t = blockIdx.x * blockDim.x + threadIdx.x;          // node*20 + c
    if (t >= NNODES * (P1 / 4)) return;
    int node = t / (P1 / 4), c = t - node * (P1 / 4);
    float4 v;
    int f = c * 4;
    v.x = (f + 0 < 78) ? x[(size_t)node * 78 + f + 0] : 0.f;
    v.y = (f + 1 < 78) ? x[(size_t)node * 78 + f + 1] : 0.f;
    v.z = (f + 2 < 78) ? x[(size_t)node * 78 + f + 2] : 0.f;
    v.w = (f + 3 < 78) ? x[(size_t)node * 78 + f + 3] : 0.f;
    xp[t] = v;
}
__global__ void k_padw(const float* __restrict__ W, float* __restrict__ Wp,
                       int K, int N, int Kp, int Np) {
    int t = blockIdx.x * blockDim.x + threadIdx.x;
    if (t >= Kp * Np) return;
    int k = t / Np, n = t - k * Np;
    Wp[t] = (k < K && n < N) ? W[(size_t)k * N + n] : 0.f;
}
__global__ void k_fillbias(float* __restrict__ C, const float* __restrict__ b,
                           int M, int N, int ldc, int coff) {
    int t = blockIdx.x * blockDim.x + threadIdx.x;
    if (t >= M * N) return;
    int m = t / N, n = t - m * N;
    C[(size_t)m * ldc + coff + n] = b[n];
}

// ---------------- packed-f32x2 GEMM: 64x64 tile, 128 threads, 8x4 micro -----
__device__ __forceinline__ void fma2(ULL& d, ULL a, ULL b) {
    asm("fma.rn.f32x2 %0, %1, %2, %0;" : "+l"(d) : "l"(a), "l"(b));
}
__global__ void __launch_bounds__(128)
k_gemm(const float* __restrict__ A, const float* __restrict__ B,
       float* __restrict__ C, int M, int N, int K, int lda,
       const float* __restrict__ bias, const float* __restrict__ rs,
       int relu, int ldc, int coff, int Kc, int split) {
    __shared__ __align__(16) float2 As2[16][64];
    __shared__ __align__(16) float  Bs[16][64];
    int tid = threadIdx.x;
    int tx = tid & 15, ty = tid >> 4;            // tx: n (16*4), ty: m (8*8)
    int bm = blockIdx.y * 64, bn = blockIdx.x * 64;
    int kbeg = blockIdx.z * Kc;
    int kend = min(K, kbeg + Kc);
    ULL acc[8][2];
#pragma unroll
    for (int i = 0; i < 8; i++) { acc[i][0] = 0ULL; acc[i][1] = 0ULL; }

    for (int k0 = kbeg; k0 < kend; k0 += 16) {
#pragma unroll
        for (int l = 0; l < 2; l++) {
            int idx = tid + l * 128;
            int m = idx >> 2, k4 = idx & 3;
            float4 v = *(const float4*)&A[(size_t)(bm + m) * lda + k0 + k4 * 4];
            As2[k4 * 4 + 0][m] = make_float2(v.x, v.x);
            As2[k4 * 4 + 1][m] = make_float2(v.y, v.y);
            As2[k4 * 4 + 2][m] = make_float2(v.z, v.z);
            As2[k4 * 4 + 3][m] = make_float2(v.w, v.w);
        }
#pragma unroll
        for (int l = 0; l < 2; l++) {
            int idx = tid + l * 128;
            int bk = idx >> 4, n4 = idx & 15;
            int n0 = bn + n4 * 4;
            float4 v = make_float4(0.f, 0.f, 0.f, 0.f);
            if (n0 < N) v = *(const float4*)&B[(size_t)(k0 + bk) * N + n0];
            *(float4*)&Bs[bk][n4 * 4] = v;
        }
        __syncthreads();
#pragma unroll
        for (int kk = 0; kk < 16; kk++) {
            ULL b2[2];
            { ulonglong2 t = *(ulonglong2*)&Bs[kk][tx * 4]; b2[0] = t.x; b2[1] = t.y; }
            ULL a2[8];
#pragma unroll
            for (int q = 0; q < 4; q++) {
                ulonglong2 t = *(ulonglong2*)&As2[kk][ty * 8 + q * 2];
                a2[q * 2] = t.x; a2[q * 2 + 1] = t.y;
            }
#pragma unroll
            for (int i = 0; i < 8; i++) {
                fma2(acc[i][0], a2[i], b2[0]);
                fma2(acc[i][1], a2[i], b2[1]);
            }
        }
        __syncthreads();
    }
#pragma unroll
    for (int i = 0; i < 8; i++) {
        int m = bm + ty * 8 + i;
        float scale = rs ? rs[m] : 1.f;
#pragma unroll
        for (int j = 0; j < 2; j++) {
            float2 v = *(float2*)&acc[i][j];
            int n = bn + tx * 4 + j * 2;
            if (n >= N) continue;
            if (split) {
                atomicAdd(&C[(size_t)m * ldc + coff + n],     v.x);
                atomicAdd(&C[(size_t)m * ldc + coff + n + 1], v.y);
            } else {
                float o0 = v.x * scale + (bias ? bias[n]     : 0.f);
                float o1 = v.y * scale + (bias ? bias[n + 1] : 0.f);
                if (relu) { o0 = fmaxf(o0, 0.f); o1 = fmaxf(o1, 0.f); }
                C[(size_t)m * ldc + coff + n]     = o0;
                C[(size_t)m * ldc + coff + n + 1] = o1;
            }
        }
    }
}

// ---------------- CSR gather aggregation, thread per (node, float4 chunk) ---
__global__ void k_aggr4(const float4* __restrict__ hws, const int* __restrict__ rowptr,
                        const int* __restrict__ col, const float* __restrict__ dinv,
                        const float* __restrict__ bias, float4* __restrict__ outp,
                        const int* __restrict__ batch, float* __restrict__ pool,
                        int ld4, int Freal, int doPool) {
    int t = blockIdx.x * blockDim.x + threadIdx.x;
    if (t >= NNODES * ld4) return;
    int node = t / ld4, c = t - node * ld4;
    float4 acc = hws[(size_t)node * ld4 + c];
    int re = rowptr[node + 1];
    for (int e = rowptr[node]; e < re; e++) {
        float4 v = hws[(size_t)col[e] * ld4 + c];
        acc.x += v.x; acc.y += v.y; acc.z += v.z; acc.w += v.w;
    }
    float di = dinv[node];
    int f0 = c * 4;
    float b0 = (f0 + 0 < Freal) ? bias[f0 + 0] : 0.f;
    float b1 = (f0 + 1 < Freal) ? bias[f0 + 1] : 0.f;
    float b2 = (f0 + 2 < Freal) ? bias[f0 + 2] : 0.f;
    float b3 = (f0 + 3 < Freal) ? bias[f0 + 3] : 0.f;
    float v0 = fmaxf(acc.x * di + b0, 0.f);
    float v1 = fmaxf(acc.y * di + b1, 0.f);
    float v2 = fmaxf(acc.z * di + b2, 0.f);
    float v3 = fmaxf(acc.w * di + b3, 0.f);
    if (doPool) {
        float* pp = pool + (size_t)batch[node] * (ld4 * 4) + f0;
        atomicMax((int*)&pp[0], __float_as_int(v0));
        atomicMax((int*)&pp[1], __float_as_int(v1));
        atomicMax((int*)&pp[2], __float_as_int(v2));
        atomicMax((int*)&pp[3], __float_as_int(v3));
    } else {
        outp[(size_t)node * ld4 + c] = make_float4(v0, v1, v2, v3);
    }
}

// ---------------- transpose Wc[32][750][8] -> Wt[750][256] -------------------
__global__ void k_transw(const float* __restrict__ W, float* __restrict__ Wt) {
    int i = blockIdx.x * blockDim.x + threadIdx.x;
    if (i >= 750 * 256) return;
    int c = i >> 8, ok = i & 255;
    int o = ok >> 3, k = ok & 7;
    Wt[i] = W[((size_t)o * 750 + c) * 8 + k];
}

// ---------------- protein branch 2: factored conv via class-histogram T ------
__global__ void k_branch2(const int* __restrict__ t2, const float* __restrict__ Wc2t,
                          const float* __restrict__ embw, const float* __restrict__ bc2,
                          float* __restrict__ Y2) {
    __shared__ float Tl[26 * 256];
    __shared__ float embs[26 * 128];
    __shared__ int   t2s[750];
    int b = blockIdx.x, tid = threadIdx.x;
    for (int i = tid; i < 26 * 256; i += 256) Tl[i] = 0.f;
    for (int i = tid; i < 26 * 128; i += 256) embs[i] = embw[i];
    for (int i = tid; i < 750; i += 256) t2s[i] = t2[(size_t)b * 750 + i];
    __syncthreads();
    for (int c = 0; c < 750; c++)
        Tl[t2s[c] * 256 + tid] += Wc2t[(size_t)c * 256 + tid];
    __syncthreads();
    for (int idx = tid; idx < 32 * 121; idx += 256) {
        int o = idx / 121, l = idx - o * 121;
        float acc = bc2[o];
        for (int v = 0; v < 26; v++) {
#pragma unroll
            for (int k = 0; k < 8; k++)
                acc += Tl[v * 256 + o * 8 + k] * embs[v * 128 + l + k];
        }
        Y2[(size_t)b * 3872 + idx] = acc;
    }
}

// ---------------- protein branch 1: direct conv ------------------------------
__global__ void k_conv1(const float* __restrict__ t1, const float* __restrict__ Wc1t,
                        const float* __restrict__ bc1, float* __restrict__ Y1) {
    __shared__ float sin_[50 * 20];
    int b = blockIdx.x, tid = threadIdx.x;
    int o = tid >> 3, k = tid & 7;
    float acc[13] = {};
    for (int c0 = 0; c0 < 750; c0 += 50) {
        for (int i = tid; i < 1000; i += 256)
            sin_[i] = t1[(size_t)b * 15000 + c0 * 20 + i];
        __syncthreads();
        for (int cc = 0; cc < 50; cc++) {
            float w = Wc1t[(size_t)(c0 + cc) * 256 + tid];
#pragma unroll
            for (int l = 0; l < 13; l++)
                acc[l] += w * sin_[cc * 20 + k + l];
        }
        __syncthreads();
    }
#pragma unroll
    for (int l = 0; l < 13; l++) {
        float v = acc[l];
        v += __shfl_down_sync(0xffffffffu, v, 4, 8);
        v += __shfl_down_sync(0xffffffffu, v, 2, 8);
        v += __shfl_down_sync(0xffffffffu, v, 1, 8);
        if (k == 0) Y1[(size_t)b * 416 + o * 13 + l] = v + bc1[o];
    }
}

// ---------------- final projection -------------------------------------------
__global__ void k_out(const float* __restrict__ F2w, const float* __restrict__ Wo,
                      const float* __restrict__ bo, float* __restrict__ out) {
    int warp = (blockIdx.x * blockDim.x + threadIdx.x) >> 5;
    int lane = threadIdx.x & 31;
    if (warp >= NGRAPH) return;
    float s = 0.f;
    for (int i = lane; i < 512; i += 32) s += F2w[(size_t)warp * 512 + i] * Wo[i];
#pragma unroll
    for (int off = 16; off; off >>= 1) s += __shfl_down_sync(0xffffffffu, s, off);
    if (lane == 0) out[warp] = s + bo[0];
}

// ---------------- host orchestration ----------------
extern "C" void kernel_launch(void* const* d_in, const int* in_sizes, int n_in,
                              void* d_out, int out_size) {
    const float* x   = (const float*)d_in[0];
    const int*   ei  = (const int*)  d_in[1];
    const int*   bat = (const int*)  d_in[2];
    const float* t1  = (const float*)d_in[3];
    const int*   t2  = (const int*)  d_in[4];
    const float *W1 = (const float*)d_in[5],  *b1 = (const float*)d_in[6];
    const float *W2 = (const float*)d_in[7],  *b2 = (const float*)d_in[8];
    const float *W3 = (const float*)d_in[9],  *b3 = (const float*)d_in[10];
    const float *Wg1= (const float*)d_in[11], *bg1= (const float*)d_in[12];
    const float *Wg2= (const float*)d_in[13], *bg2= (const float*)d_in[14];
    const float *emb= (const float*)d_in[15];
    const float *Wc2= (const float*)d_in[16], *bc2= (const float*)d_in[17];
    const float *Wxt2=(const float*)d_in[18], *bxt2=(const float*)d_in[19];
    const float *Wc1= (const float*)d_in[20], *bc1= (const float*)d_in[21];
    const float *Wxt1=(const float*)d_in[22], *bxt1=(const float*)d_in[23];
    const float *Wf1= (const float*)d_in[24], *bf1= (const float*)d_in[25];
    const float *Wf2= (const float*)d_in[26], *bf2= (const float*)d_in[27];
    const float *Wo = (const float*)d_in[28], *bo = (const float*)d_in[29];
    float* out = (float*)d_out;

    float *X80, *B1, *B2, *dinv, *G, *G1, *XC, *Y2, *Y1, *Fb1, *Fb2, *Wc2t, *Wc1t;
    float *W1p, *W2p, *W3p, *Wg1p;
    int *cnt, *rowptr, *cur, *col;
    cudaGetSymbolAddress((void**)&X80, g_X80);
    cudaGetSymbolAddress((void**)&B1, g_B1);
    cudaGetSymbolAddress((void**)&B2, g_B2);
    cudaGetSymbolAddress((void**)&dinv, g_dinv);
    cudaGetSymbolAddress((void**)&cnt, g_cnt);
    cudaGetSymbolAddress((void**)&rowptr, g_rowptr);
    cudaGetSymbolAddress((void**)&cur, g_cur);
    cudaGetSymbolAddress((void**)&col, g_col);
    cudaGetSymbolAddress((void**)&G, g_G);
    cudaGetSymbolAddress((void**)&G1, g_G1);
    cudaGetSymbolAddress((void**)&XC, g_XC);
    cudaGetSymbolAddress((void**)&Y2, g_Y2);
    cudaGetSymbolAddress((void**)&Y1, g_Y1);
    cudaGetSymbolAddress((void**)&Fb1, g_F1);
    cudaGetSymbolAddress((void**)&Fb2, g_F2);
    cudaGetSymbolAddress((void**)&Wc2t, g_Wc2t);
    cudaGetSymbolAddress((void**)&Wc1t, g_Wc1t);
    cudaGetSymbolAddress((void**)&W1p, g_W1p);
    cudaGetSymbolAddress((void**)&W2p, g_W2p);
    cudaGetSymbolAddress((void**)&W3p, g_W3p);
    cudaGetSymbolAddress((void**)&Wg1p, g_Wg1p);

    const int N = NNODES, E = NEDGES;

    // ---- CSR + padding prep ----
    cudaMemsetAsync(cnt, 0, N * sizeof(int));
    cudaMemsetAsync(G, 0, (size_t)NGRAPH * P3 * sizeof(float));
    k_hist   <<<(E + 255) / 256, 256>>>(ei, cnt, E);
    k_scan   <<<1, 1024>>>(cnt, rowptr, cur, dinv);
    k_scatter<<<(E + 255) / 256, 256>>>(ei, cur, col, E);
    k_padx   <<<(N * (P1/4) + 255) / 256, 256>>>(x, (float4*)X80);
    k_padw   <<<(P1*P1 + 255) / 256, 256>>>(W1, W1p, 78, 78, P1, P1);
    k_padw   <<<(P1*P2 + 255) / 256, 256>>>(W2, W2p, 78, 156, P1, P2);
    k_padw   <<<(P2*P3 + 255) / 256, 256>>>(W3, W3p, 156, 312, P2, P3);
    k_padw   <<<(P3*1024 + 255) / 256, 256>>>(Wg1, Wg1p, 312, 1024, P3, 1024);

    // ---- GCN layers (A rows pre-scaled by dinv via rs) ----
    k_gemm<<<dim3(P1/64 + 1, N/64, 1), 128>>>(X80, W1p, B2, N, P1, P1, P1, nullptr, dinv, 0, P1, 0, P1, 0);
    k_aggr4<<<(N*(P1/4) + 255)/256, 256>>>((float4*)B2, rowptr, col, dinv, b1, (float4*)B1, nullptr, nullptr, P1/4, 78, 0);
    k_gemm<<<dim3(P2/64 + 1, N/64, 1), 128>>>(B1, W2p, B2, N, P2, P1, P1, nullptr, dinv, 0, P2, 0, P1, 0);
    k_aggr4<<<(N*(P2/4) + 255)/256, 256>>>((float4*)B2, rowptr, col, dinv, b2, (float4*)B1, nullptr, nullptr, P2/4, 156, 0);
    k_gemm<<<dim3(P3/64, N/64, 1), 128>>>(B1, W3p, B2, N, P3, P2, P2, nullptr, dinv, 0, P3, 0, P2, 0);
    k_aggr4<<<(N*(P3/4) + 255)/256, 256>>>((float4*)B2, rowptr, col, dinv, b3, nullptr, bat, G, P3/4, 312, 1);

    // ---- graph head ----
    k_gemm<<<dim3(16, 16, 1), 128>>>(G, Wg1p, G1, NGRAPH, 1024, P3, P3, bg1, nullptr, 1, 1024, 0, P3, 0);
    k_fillbias<<<(NGRAPH*128 + 255)/256, 256>>>(XC, bg2, NGRAPH, 128, 384, 0);
    k_gemm<<<dim3(2, 16, 8), 128>>>(G1, Wg2, XC, NGRAPH, 128, 1024, 1024, nullptr, nullptr, 0, 384, 0, 128, 1);

    // ---- protein branch 2 -> XC[:,256:384] ----
    k_transw<<<750, 256>>>(Wc2, Wc2t);
    k_branch2<<<NGRAPH, 256>>>(t2, Wc2t, emb, bc2, Y2);
    k_fillbias<<<(NGRAPH*128 + 255)/256, 256>>>(XC, bxt2, NGRAPH, 128, 384, 256);
    k_gemm<<<dim3(2, 16, 11), 128>>>(Y2, Wxt2, XC, NGRAPH, 128, 3872, 3872, nullptr, nullptr, 0, 384, 256, 352, 1);

    // ---- protein branch 1 -> XC[:,128:256] ----
    k_transw<<<750, 256>>>(Wc1, Wc1t);
    k_conv1<<<NGRAPH, 256>>>(t1, Wc1t, bc1, Y1);
    k_fillbias<<<(NGRAPH*128 + 255)/256, 256>>>(XC, bxt1, NGRAPH, 128, 384, 128);
    k_gemm<<<dim3(2, 16, 4), 128>>>(Y1, Wxt1, XC, NGRAPH, 128, 416, 416, nullptr, nullptr, 0, 384, 128, 112, 1);

    // ---- fusion head ----
    k_gemm<<<dim3(16, 16, 1), 128>>>(XC, Wf1, Fb1, NGRAPH, 1024, 384, 384, bf1, nullptr, 1, 1024, 0, 384, 0);
    k_gemm<<<dim3(8, 16, 1), 128>>>(Fb1, Wf2, Fb2, NGRAPH, 512, 1024, 1024, bf2, nullptr, 1, 512, 0, 1024, 0);
    k_out<<<(NGRAPH * 32 + 255) / 256, 256>>>(Fb2, Wo, bo, out);
}

// round 4
// speedup vs baseline: 2.3341x; 1.0158x over previous
#include <cuda_runtime.h>
#include <cuda_bf16.h>
#include <math.h>

#define NNODES 40960
#define NEDGES 163840
#define NGRAPH 1024
typedef unsigned long long ULL;

// padded feature dims (multiples of 16)
#define P1 80
#define P2 160
#define P3 320

// ---------------- static scratch ----------------
__device__ __align__(16) float g_X80[NNODES * P1];
__device__ __align__(16) float g_B1[NNODES * P3];
__device__ __align__(16) float g_B2[NNODES * P3];
__device__ float g_dinv[NNODES];
__device__ int   g_cnt[NNODES];
__device__ int   g_rowptr[NNODES + 1];
__device__ int   g_cur[NNODES];
__device__ int   g_col[NEDGES];
__device__ __align__(16) float g_G[NGRAPH * P3];
__device__ __align__(16) float g_G1[NGRAPH * 1024];
__device__ __align__(16) float g_XC[NGRAPH * 384];
__device__ __align__(16) float g_Y2[NGRAPH * 3872];
__device__ __align__(16) float g_Y1[NGRAPH * 416];
__device__ __align__(16) float g_F1[NGRAPH * 1024];
__device__ __align__(16) float g_F2[NGRAPH * 512];
__device__ __align__(16) float g_Wc2t[750 * 256];
__device__ __align__(16) float g_Wc1t[750 * 256];
__device__ __align__(16) float g_W1p[P1 * P1];
__device__ __align__(16) float g_W2p[P1 * P2];
__device__ __align__(16) float g_W3p[P2 * P3];
__device__ __align__(16) float g_Wg1p[P3 * 1024];
__device__ __align__(16) float g_b1p[P1];
__device__ __align__(16) float g_b2p[P2];
__device__ __align__(16) float g_b3p[P3];

// ---------------- CSR build ----------------
__global__ void k_hist(const int* __restrict__ ei, int* __restrict__ cnt, int e) {
    int i = blockIdx.x * blockDim.x + threadIdx.x;
    if (i < e) atomicAdd(&cnt[ei[e + i]], 1);
}
__global__ void k_scan(const int* __restrict__ cnt, int* __restrict__ rowptr,
                       int* __restrict__ cur, float* __restrict__ dinv) {
    __shared__ int ssum[1024];
    int t = threadIdx.x;
    const int CH = NNODES / 1024;
    int base = t * CH;
    int s = 0;
    for (int i = 0; i < CH; i++) s += cnt[base + i];
    ssum[t] = s;
    __syncthreads();
    for (int off = 1; off < 1024; off <<= 1) {
        int v = (t >= off) ? ssum[t - off] : 0;
        __syncthreads();
        ssum[t] += v;
        __syncthreads();
    }
    int run = ssum[t] - s;
    for (int i = 0; i < CH; i++) {
        int c = cnt[base + i];
        rowptr[base + i] = run;
        cur[base + i]    = run;
        dinv[base + i]   = rsqrtf((float)c + 1.0f);
        run += c;
    }
    if (t == 1023) rowptr[NNODES] = run;
}
__global__ void k_scatter(const int* __restrict__ ei, int* __restrict__ cur,
                          int* __restrict__ col, int e) {
    int i = blockIdx.x * blockDim.x + threadIdx.x;
    if (i >= e) return;
    int s = ei[i], d = ei[e + i];
    int pos = atomicAdd(&cur[d], 1);
    col[pos] = s;
}

// ---------------- padding kernels ----------------
// X' = dinv[node] * x, padded to 80
__global__ void k_padx(const float* __restrict__ x, const float* __restrict__ dinv,
                       float4* __restrict__ xp) {
    int t = blockIdx.x * blockDim.x + threadIdx.x;
    if (t >= NNODES * (P1 / 4)) return;
    int node = t / (P1 / 4), c = t - node * (P1 / 4);
    float di = dinv[node];
    float4 v;
    int f = c * 4;
    v.x = (f + 0 < 78) ? di * x[(size_t)node * 78 + f + 0] : 0.f;
    v.y = (f + 1 < 78) ? di * x[(size_t)node * 78 + f + 1] : 0.f;
    v.z = (f + 2 < 78) ? di * x[(size_t)node * 78 + f + 2] : 0.f;
    v.w = (f + 3 < 78) ? di * x[(size_t)node * 78 + f + 3] : 0.f;
    xp[t] = v;
}
__global__ void k_padw(const float* __restrict__ W, float* __restrict__ Wp,
                       int K, int N, int Kp, int Np) {
    int t = blockIdx.x * blockDim.x + threadIdx.x;
    if (t >= Kp * Np) return;
    int k = t / Np, n = t - k * Np;
    Wp[t] = (k < K && n < N) ? W[(size_t)k * N + n] : 0.f;
}
__global__ void k_fillbias(float* __restrict__ C, const float* __restrict__ b,
                           int M, int N, int ldc, int coff) {
    int t = blockIdx.x * blockDim.x + threadIdx.x;
    if (t >= M * N) return;
    int m = t / N, n = t - m * N;
    C[(size_t)m * ldc + coff + n] = b[n];
}

// ---------------- packed-f32x2 GEMM: 64x64 tile, 128 threads, 8x4 micro -----
// epilogue: o = acc + bias; if(relu) relu; o *= rs[m];
//   split: atomicAdd into C (bias preloaded)
//   pool:  atomicMax into C[bat[m]*ldc + n]
__device__ __forceinline__ void fma2(ULL& d, ULL a, ULL b) {
    asm("fma.rn.f32x2 %0, %1, %2, %0;" : "+l"(d) : "l"(a), "l"(b));
}
__global__ void __launch_bounds__(128)
k_gemm(const float* __restrict__ A, const float* __restrict__ B,
       float* __restrict__ C, int M, int N, int K, int lda,
       const float* __restrict__ bias, const float* __restrict__ rs,
       int relu, int ldc, int coff, int Kc, int split,
       const int* __restrict__ bat) {
    __shared__ __align__(16) float2 As2[16][64];
    __shared__ __align__(16) float  Bs[16][64];
    int tid = threadIdx.x;
    int tx = tid & 15, ty = tid >> 4;
    int bm = blockIdx.y * 64, bn = blockIdx.x * 64;
    int kbeg = blockIdx.z * Kc;
    int kend = min(K, kbeg + Kc);
    ULL acc[8][2];
#pragma unroll
    for (int i = 0; i < 8; i++) { acc[i][0] = 0ULL; acc[i][1] = 0ULL; }

    for (int k0 = kbeg; k0 < kend; k0 += 16) {
#pragma unroll
        for (int l = 0; l < 2; l++) {
            int idx = tid + l * 128;
            int m = idx >> 2, k4 = idx & 3;
            float4 v = *(const float4*)&A[(size_t)(bm + m) * lda + k0 + k4 * 4];
            As2[k4 * 4 + 0][m] = make_float2(v.x, v.x);
            As2[k4 * 4 + 1][m] = make_float2(v.y, v.y);
            As2[k4 * 4 + 2][m] = make_float2(v.z, v.z);
            As2[k4 * 4 + 3][m] = make_float2(v.w, v.w);
        }
#pragma unroll
        for (int l = 0; l < 2; l++) {
            int idx = tid + l * 128;
            int bk = idx >> 4, n4 = idx & 15;
            int n0 = bn + n4 * 4;
            float4 v = make_float4(0.f, 0.f, 0.f, 0.f);
            if (n0 < N) v = *(const float4*)&B[(size_t)(k0 + bk) * N + n0];
            *(float4*)&Bs[bk][n4 * 4] = v;
        }
        __syncthreads();
#pragma unroll
        for (int kk = 0; kk < 16; kk++) {
            ULL b2[2];
            { ulonglong2 t = *(ulonglong2*)&Bs[kk][tx * 4]; b2[0] = t.x; b2[1] = t.y; }
            ULL a2[8];
#pragma unroll
            for (int q = 0; q < 4; q++) {
                ulonglong2 t = *(ulonglong2*)&As2[kk][ty * 8 + q * 2];
                a2[q * 2] = t.x; a2[q * 2 + 1] = t.y;
            }
#pragma unroll
            for (int i = 0; i < 8; i++) {
                fma2(acc[i][0], a2[i], b2[0]);
                fma2(acc[i][1], a2[i], b2[1]);
            }
        }
        __syncthreads();
    }
#pragma unroll
    for (int i = 0; i < 8; i++) {
        int m = bm + ty * 8 + i;
        float scale = rs ? rs[m] : 1.f;
        int poolRow = bat ? bat[m] : 0;
#pragma unroll
        for (int j = 0; j < 2; j++) {
            float2 v = *(float2*)&acc[i][j];
            int n = bn + tx * 4 + j * 2;
            if (n >= N) continue;
            if (split) {
                atomicAdd(&C[(size_t)m * ldc + coff + n],     v.x);
                atomicAdd(&C[(size_t)m * ldc + coff + n + 1], v.y);
            } else if (bat) {
                float o0 = fmaxf(v.x + (bias ? bias[n]     : 0.f), 0.f);
                float o1 = fmaxf(v.y + (bias ? bias[n + 1] : 0.f), 0.f);
                float* pp = &C[(size_t)poolRow * ldc + n];
                atomicMax((int*)&pp[0], __float_as_int(o0));
                atomicMax((int*)&pp[1], __float_as_int(o1));
            } else {
                float o0 = v.x + (bias ? bias[n]     : 0.f);
                float o1 = v.y + (bias ? bias[n + 1] : 0.f);
                if (relu) { o0 = fmaxf(o0, 0.f); o1 = fmaxf(o1, 0.f); }
                o0 *= scale; o1 *= scale;
                C[(size_t)m * ldc + coff + n]     = o0;
                C[(size_t)m * ldc + coff + n + 1] = o1;
            }
        }
    }
}

// ---------------- CSR gather: out[d] = dinv[d] * (h'[d] + sum_nbr h'[s]) -----
__global__ void k_aggr4(const float4* __restrict__ hws, const int* __restrict__ rowptr,
                        const int* __restrict__ col, const float* __restrict__ dinv,
                        float4* __restrict__ outp, int ld4) {
    int t = blockIdx.x * blockDim.x + threadIdx.x;
    if (t >= NNODES * ld4) return;
    int node = t / ld4, c = t - node * ld4;
    float4 acc = hws[(size_t)node * ld4 + c];
    int re = rowptr[node + 1];
    for (int e = rowptr[node]; e < re; e++) {
        float4 v = hws[(size_t)col[e] * ld4 + c];
        acc.x += v.x; acc.y += v.y; acc.z += v.z; acc.w += v.w;
    }
    float di = dinv[node];
    outp[(size_t)node * ld4 + c] = make_float4(acc.x * di, acc.y * di, acc.z * di, acc.w * di);
}

// ---------------- transpose Wc[32][750][8] -> Wt[750][256] -------------------
__global__ void k_transw(const float* __restrict__ W, float* __restrict__ Wt) {
    int i = blockIdx.x * blockDim.x + threadIdx.x;
    if (i >= 750 * 256) return;
    int c = i >> 8, ok = i & 255;
    int o = ok >> 3, k = ok & 7;
    Wt[i] = W[((size_t)o * 750 + c) * 8 + k];
}

// ---------------- protein branch 2: factored conv via class-histogram T ------
__global__ void k_branch2(const int* __restrict__ t2, const float* __restrict__ Wc2t,
                          const float* __restrict__ embw, const float* __restrict__ bc2,
                          float* __restrict__ Y2) {
    __shared__ float Tl[26 * 256];
    __shared__ float embs[26 * 128];
    __shared__ int   t2s[750];
    int b = blockIdx.x, tid = threadIdx.x;
    for (int i = tid; i < 26 * 256; i += 256) Tl[i] = 0.f;
    for (int i = tid; i < 26 * 128; i += 256) embs[i] = embw[i];
    for (int i = tid; i < 750; i += 256) t2s[i] = t2[(size_t)b * 750 + i];
    __syncthreads();
    for (int c = 0; c < 750; c++)
        Tl[t2s[c] * 256 + tid] += Wc2t[(size_t)c * 256 + tid];
    __syncthreads();
    for (int idx = tid; idx < 32 * 121; idx += 256) {
        int o = idx / 121, l = idx - o * 121;
        float acc = bc2[o];
        for (int v = 0; v < 26; v++) {
#pragma unroll
            for (int k = 0; k < 8; k++)
                acc += Tl[v * 256 + o * 8 + k] * embs[v * 128 + l + k];
        }
        Y2[(size_t)b * 3872 + idx] = acc;
    }
}

// ---------------- protein branch 1: direct conv ------------------------------
__global__ void k_conv1(const float* __restrict__ t1, const float* __restrict__ Wc1t,
                        const float* __restrict__ bc1, float* __restrict__ Y1) {
    __shared__ float sin_[50 * 20];
    int b = blockIdx.x, tid = threadIdx.x;
    int o = tid >> 3, k = tid & 7;
    float acc[13] = {};
    for (int c0 = 0; c0 < 750; c0 += 50) {
        for (int i = tid; i < 1000; i += 256)
            sin_[i] = t1[(size_t)b * 15000 + c0 * 20 + i];
        __syncthreads();
        for (int cc = 0; cc < 50; cc++) {
            float w = Wc1t[(size_t)(c0 + cc) * 256 + tid];
#pragma unroll
            for (int l = 0; l < 13; l++)
                acc[l] += w * sin_[cc * 20 + k + l];
        }
        __syncthreads();
    }
#pragma unroll
    for (int l = 0; l < 13; l++) {
        float v = acc[l];
        v += __shfl_down_sync(0xffffffffu, v, 4, 8);
        v += __shfl_down_sync(0xffffffffu, v, 2, 8);
        v += __shfl_down_sync(0xffffffffu, v, 1, 8);
        if (k == 0) Y1[(size_t)b * 416 + o * 13 + l] = v + bc1[o];
    }
}

// ---------------- final projection -------------------------------------------
__global__ void k_out(const float* __restrict__ F2w, const float* __restrict__ Wo,
                      const float* __restrict__ bo, float* __restrict__ out) {
    int warp = (blockIdx.x * blockDim.x + threadIdx.x) >> 5;
    int lane = threadIdx.x & 31;
    if (warp >= NGRAPH) return;
    float s = 0.f;
    for (int i = lane; i < 512; i += 32) s += F2w[(size_t)warp * 512 + i] * Wo[i];
#pragma unroll
    for (int off = 16; off; off >>= 1) s += __shfl_down_sync(0xffffffffu, s, off);
    if (lane == 0) out[warp] = s + bo[0];
}

// ---------------- host orchestration ----------------
extern "C" void kernel_launch(void* const* d_in, const int* in_sizes, int n_in,
                              void* d_out, int out_size) {
    const float* x   = (const float*)d_in[0];
    const int*   ei  = (const int*)  d_in[1];
    const int*   bat = (const int*)  d_in[2];
    const float* t1  = (const float*)d_in[3];
    const int*   t2  = (const int*)  d_in[4];
    const float *W1 = (const float*)d_in[5],  *b1 = (const float*)d_in[6];
    const float *W2 = (const float*)d_in[7],  *b2 = (const float*)d_in[8];
    const float *W3 = (const float*)d_in[9],  *b3 = (const float*)d_in[10];
    const float *Wg1= (const float*)d_in[11], *bg1= (const float*)d_in[12];
    const float *Wg2= (const float*)d_in[13], *bg2= (const float*)d_in[14];
    const float *emb= (const float*)d_in[15];
    const float *Wc2= (const float*)d_in[16], *bc2= (const float*)d_in[17];
    const float *Wxt2=(const float*)d_in[18], *bxt2=(const float*)d_in[19];
    const float *Wc1= (const float*)d_in[20], *bc1= (const float*)d_in[21];
    const float *Wxt1=(const float*)d_in[22], *bxt1=(const float*)d_in[23];
    const float *Wf1= (const float*)d_in[24], *bf1= (const float*)d_in[25];
    const float *Wf2= (const float*)d_in[26], *bf2= (const float*)d_in[27];
    const float *Wo = (const float*)d_in[28], *bo = (const float*)d_in[29];
    float* out = (float*)d_out;

    float *X80, *B1, *B2, *dinv, *G, *G1, *XC, *Y2, *Y1, *Fb1, *Fb2, *Wc2t, *Wc1t;
    float *W1p, *W2p, *W3p, *Wg1p, *b1p, *b2p, *b3p;
    int *cnt, *rowptr, *cur, *col;
    cudaGetSymbolAddress((void**)&X80, g_X80);
    cudaGetSymbolAddress((void**)&B1, g_B1);
    cudaGetSymbolAddress((void**)&B2, g_B2);
    cudaGetSymbolAddress((void**)&dinv, g_dinv);
    cudaGetSymbolAddress((void**)&cnt, g_cnt);
    cudaGetSymbolAddress((void**)&rowptr, g_rowptr);
    cudaGetSymbolAddress((void**)&cur, g_cur);
    cudaGetSymbolAddress((void**)&col, g_col);
    cudaGetSymbolAddress((void**)&G, g_G);
    cudaGetSymbolAddress((void**)&G1, g_G1);
    cudaGetSymbolAddress((void**)&XC, g_XC);
    cudaGetSymbolAddress((void**)&Y2, g_Y2);
    cudaGetSymbolAddress((void**)&Y1, g_Y1);
    cudaGetSymbolAddress((void**)&Fb1, g_F1);
    cudaGetSymbolAddress((void**)&Fb2, g_F2);
    cudaGetSymbolAddress((void**)&Wc2t, g_Wc2t);
    cudaGetSymbolAddress((void**)&Wc1t, g_Wc1t);
    cudaGetSymbolAddress((void**)&W1p, g_W1p);
    cudaGetSymbolAddress((void**)&W2p, g_W2p);
    cudaGetSymbolAddress((void**)&W3p, g_W3p);
    cudaGetSymbolAddress((void**)&Wg1p, g_Wg1p);
    cudaGetSymbolAddress((void**)&b1p, g_b1p);
    cudaGetSymbolAddress((void**)&b2p, g_b2p);
    cudaGetSymbolAddress((void**)&b3p, g_b3p);

    const int N = NNODES, E = NEDGES;

    // ---- CSR + padding prep ----
    cudaMemsetAsync(cnt, 0, N * sizeof(int));
    cudaMemsetAsync(G, 0, (size_t)NGRAPH * P3 * sizeof(float));
    k_hist   <<<(E + 255) / 256, 256>>>(ei, cnt, E);
    k_scan   <<<1, 1024>>>(cnt, rowptr, cur, dinv);
    k_scatter<<<(E + 255) / 256, 256>>>(ei, cur, col, E);
    k_padx   <<<(N * (P1/4) + 255) / 256, 256>>>(x, dinv, (float4*)X80);
    k_padw   <<<(P1*P1 + 255) / 256, 256>>>(W1, W1p, 78, 78, P1, P1);
    k_padw   <<<(P1*P2 + 255) / 256, 256>>>(W2, W2p, 78, 156, P1, P2);
    k_padw   <<<(P2*P3 + 255) / 256, 256>>>(W3, W3p, 156, 312, P2, P3);
    k_padw   <<<(P3*1024 + 255) / 256, 256>>>(Wg1, Wg1p, 312, 1024, P3, 1024);
    k_padw   <<<1, P1>>>(b1, b1p, 1, 78, 1, P1);
    k_padw   <<<1, P2>>>(b2, b2p, 1, 156, 1, P2);
    k_padw   <<<1, P3>>>(b3, b3p, 1, 312, 1, P3);

    // ---- GCN: aggregate-then-GEMM (linearity), h' = dinv*relu(a@W + b) ----
    k_aggr4<<<(N*(P1/4) + 255)/256, 256>>>((float4*)X80, rowptr, col, dinv, (float4*)B1, P1/4);
    k_gemm<<<dim3(2, N/64, 1), 128>>>(B1, W1p, B2, N, P1, P1, P1, b1p, dinv, 1, P1, 0, P1, 0, nullptr);
    k_aggr4<<<(N*(P1/4) + 255)/256, 256>>>((float4*)B2, rowptr, col, dinv, (float4*)B1, P1/4);
    k_gemm<<<dim3(3, N/64, 1), 128>>>(B1, W2p, B2, N, P2, P1, P1, b2p, dinv, 1, P2, 0, P1, 0, nullptr);
    k_aggr4<<<(N*(P2/4) + 255)/256, 256>>>((float4*)B2, rowptr, col, dinv, (float4*)B1, P2/4);
    // layer 3: GEMM with fused relu + per-graph max-pool into G
    k_gemm<<<dim3(5, N/64, 1), 128>>>(B1, W3p, G, N, P3, P2, P2, b3p, nullptr, 1, P3, 0, P2, 0, bat);

    // ---- graph head ----
    k_gemm<<<dim3(16, 16, 1), 128>>>(G, Wg1p, G1, NGRAPH, 1024, P3, P3, bg1, nullptr, 1, 1024, 0, P3, 0, nullptr);
    k_fillbias<<<(NGRAPH*128 + 255)/256, 256>>>(XC, bg2, NGRAPH, 128, 384, 0);
    k_gemm<<<dim3(2, 16, 8), 128>>>(G1, Wg2, XC, NGRAPH, 128, 1024, 1024, nullptr, nullptr, 0, 384, 0, 128, 1, nullptr);

    // ---- protein branch 2 -> XC[:,256:384] ----
    k_transw<<<750, 256>>>(Wc2, Wc2t);
    k_branch2<<<NGRAPH, 256>>>(t2, Wc2t, emb, bc2, Y2);
    k_fillbias<<<(NGRAPH*128 + 255)/256, 256>>>(XC, bxt2, NGRAPH, 128, 384, 256);
    k_gemm<<<dim3(2, 16, 11), 128>>>(Y2, Wxt2, XC, NGRAPH, 128, 3872, 3872, nullptr, nullptr, 0, 384, 256, 352, 1, nullptr);

    // ---- protein branch 1 -> XC[:,128:256] ----
    k_transw<<<750, 256>>>(Wc1, Wc1t);
    k_conv1<<<NGRAPH, 256>>>(t1, Wc1t, bc1, Y1);
    k_fillbias<<<(NGRAPH*128 + 255)/256, 256>>>(XC, bxt1, NGRAPH, 128, 384, 128);
    k_gemm<<<dim3(2, 16, 4), 128>>>(Y1, Wxt1, XC, NGRAPH, 128, 416, 416, nullptr, nullptr, 0, 384, 128, 112, 1, nullptr);

    // ---- fusion head ----
    k_gemm<<<dim3(16, 16, 1), 128>>>(XC, Wf1, Fb1, NGRAPH, 1024, 384, 384, bf1, nullptr, 1, 1024, 0, 384, 0, nullptr);
    k_gemm<<<dim3(8, 16, 1), 128>>>(Fb1, Wf2, Fb2, NGRAPH, 512, 1024, 1024, bf2, nullptr, 1, 512, 0, 1024, 0, nullptr);
    k_out<<<(NGRAPH * 32 + 255) / 256, 256>>>(Fb2, Wo, bo, out);
}